// round 11
// baseline (speedup 1.0000x reference)
#include <cuda_runtime.h>
#include <cuda_bf16.h>
#include <cstdint>

#define NN 50000
#define NE 800000
#define C 128
#define EK 3
#define LRELU_ALPHA 0.2f
#define SCAN_T 1024
#define RSTRIDE 80          // smem row stride in bytes
#define STAGE_BYTES 40960   // Ah(10240) Al(10240) Bh(10240) Bl(10240)

// ---------------- scratch ----------------------------------------------------
__device__ float  g_Wh[(size_t)NN * C];
__device__ float  g_s1[NN], g_s2[NN];
__device__ float4 g_edata[NE];                 // {src_bits, ex0, ex1, ex2} CSR order
__device__ float  g_agg[(size_t)NN * EK * C];
__device__ int    g_cnt[NN], g_off[NN + 1], g_pos[NN];
__device__ int    g_is64;
__device__ __align__(16) __nv_bfloat16 g_BtWHi[C * C],      g_BtWLo[C * C];
__device__ __align__(16) __nv_bfloat16 g_BtOHi[EK * C * C], g_BtOLo[EK * C * C];

// ---------------- bf16 split GEMM (tensor cores, mma.sync) -------------------
#define MMA_BF16(c, a, b0, b1)                                                 \
    asm volatile(                                                              \
        "mma.sync.aligned.m16n8k16.row.col.f32.bf16.bf16.f32 "                 \
        "{%0,%1,%2,%3}, {%4,%5,%6,%7}, {%8,%9}, {%0,%1,%2,%3};"                \
        : "+f"(c[0]), "+f"(c[1]), "+f"(c[2]), "+f"(c[3])                       \
        : "r"(a[0]), "r"(a[1]), "r"(a[2]), "r"(a[3]), "r"(b0), "r"(b1))

__device__ __forceinline__ uint pack_hi(float x, float y, uint& lo_out) {
    __nv_bfloat16 hx = __float2bfloat16_rn(x);
    __nv_bfloat16 hy = __float2bfloat16_rn(y);
    float lx = x - __bfloat162float(hx);
    float ly = y - __bfloat162float(hy);
    __nv_bfloat16 lxb = __float2bfloat16_rn(lx);
    __nv_bfloat16 lyb = __float2bfloat16_rn(ly);
    lo_out = (uint)__bfloat16_as_ushort(lxb) | ((uint)__bfloat16_as_ushort(lyb) << 16);
    return (uint)__bfloat16_as_ushort(hx) | ((uint)__bfloat16_as_ushort(hy) << 16);
}

// C[M,128] = A[M,KTOT] (f32, split in-kernel) @ Bt[128,KTOT]^T (pre-split bf16)
// 512 threads, 16 warps in a 4(M) x 4(N) grid, warp tile 32x32.
template <int KTOT, bool SCORES>
__global__ __launch_bounds__(512) void bf16gemm(
    const float* __restrict__ A,
    const __nv_bfloat16* __restrict__ BtHi, const __nv_bfloat16* __restrict__ BtLo,
    float* __restrict__ Cm, int M,
    const float* __restrict__ a1, const float* __restrict__ a2)
{
    extern __shared__ char smem[];
    const int NT = KTOT / 32;

    int tid = threadIdx.x, lane = tid & 31, wid = tid >> 5;
    int gid = lane >> 2, tig = lane & 3;
    int warp_m = wid & 3, warp_n = wid >> 2;
    int row0 = blockIdx.x * 128;

    float acc[2][4][4] = {};
    float4 av[2];
    uint4  bh4, bl4;

    auto ldg_tile = [&](int t) {
#pragma unroll
        for (int i = 0; i < 2; ++i) {
            int idx = tid + i * 512;
            int r = idx >> 3, c4 = idx & 7;
            int gr = row0 + r;
            av[i] = (gr < M)
                ? __ldcs(reinterpret_cast<const float4*>(A) + (size_t)gr * (KTOT / 4) + t * 8 + c4)
                : make_float4(0.f, 0.f, 0.f, 0.f);
        }
        {
            int n = tid >> 2, c8 = tid & 3;
            size_t base = ((size_t)n * KTOT + (size_t)t * 32) >> 3;
            bh4 = reinterpret_cast<const uint4*>(BtHi)[base + c8];
            bl4 = reinterpret_cast<const uint4*>(BtLo)[base + c8];
        }
    };
    auto sts_tile = [&](int s) {
        char* st = smem + s * STAGE_BYTES;
#pragma unroll
        for (int i = 0; i < 2; ++i) {
            int idx = tid + i * 512;
            int r = idx >> 3, c4 = idx & 7;
            uint l01, l23;
            uint h01 = pack_hi(av[i].x, av[i].y, l01);
            uint h23 = pack_hi(av[i].z, av[i].w, l23);
            *reinterpret_cast<uint2*>(st + r * RSTRIDE + c4 * 8)         = make_uint2(h01, h23);
            *reinterpret_cast<uint2*>(st + 10240 + r * RSTRIDE + c4 * 8) = make_uint2(l01, l23);
        }
        {
            int n = tid >> 2, c8 = tid & 3;
            *reinterpret_cast<uint4*>(st + 20480 + n * RSTRIDE + c8 * 16) = bh4;
            *reinterpret_cast<uint4*>(st + 30720 + n * RSTRIDE + c8 * 16) = bl4;
        }
    };

    ldg_tile(0);
    sts_tile(0);
    __syncthreads();

    for (int t = 0; t < NT; ++t) {
        if (t + 1 < NT) ldg_tile(t + 1);
        const char* st = smem + (t & 1) * STAGE_BYTES;
#pragma unroll
        for (int ks = 0; ks < 2; ++ks) {
            int kb = ks * 32;
            uint ah[2][4], al[2][4];
#pragma unroll
            for (int mt = 0; mt < 2; ++mt) {
                int r0 = warp_m * 32 + mt * 16 + gid;
                const char* p0 = st + r0 * RSTRIDE + kb + tig * 4;
                ah[mt][0] = *reinterpret_cast<const uint*>(p0);
                ah[mt][1] = *reinterpret_cast<const uint*>(p0 + 8 * RSTRIDE);
                ah[mt][2] = *reinterpret_cast<const uint*>(p0 + 16);
                ah[mt][3] = *reinterpret_cast<const uint*>(p0 + 8 * RSTRIDE + 16);
                const char* p1 = p0 + 10240;
                al[mt][0] = *reinterpret_cast<const uint*>(p1);
                al[mt][1] = *reinterpret_cast<const uint*>(p1 + 8 * RSTRIDE);
                al[mt][2] = *reinterpret_cast<const uint*>(p1 + 16);
                al[mt][3] = *reinterpret_cast<const uint*>(p1 + 8 * RSTRIDE + 16);
            }
#pragma unroll
            for (int nt = 0; nt < 4; ++nt) {
                int n0 = warp_n * 32 + nt * 8 + gid;
                const char* q = st + 20480 + n0 * RSTRIDE + kb + tig * 4;
                uint b0h = *reinterpret_cast<const uint*>(q);
                uint b1h = *reinterpret_cast<const uint*>(q + 16);
                uint b0l = *reinterpret_cast<const uint*>(q + 10240);
                uint b1l = *reinterpret_cast<const uint*>(q + 10240 + 16);
#pragma unroll
                for (int mt = 0; mt < 2; ++mt) {
                    MMA_BF16(acc[mt][nt], ah[mt], b0h, b1h);
                    MMA_BF16(acc[mt][nt], ah[mt], b0l, b1l);
                    MMA_BF16(acc[mt][nt], al[mt], b0h, b1h);
                }
            }
        }
        if (t + 1 < NT) sts_tile((t + 1) & 1);
        __syncthreads();
    }

    // C store
#pragma unroll
    for (int mt = 0; mt < 2; ++mt)
#pragma unroll
        for (int nt = 0; nt < 4; ++nt) {
            int r1 = row0 + warp_m * 32 + mt * 16 + gid;
            int r2 = r1 + 8;
            int cc = warp_n * 32 + nt * 8 + tig * 2;
            if (r1 < M)
                *reinterpret_cast<float2*>(Cm + (size_t)r1 * C + cc) =
                    make_float2(acc[mt][nt][0], acc[mt][nt][1]);
            if (r2 < M)
                *reinterpret_cast<float2*>(Cm + (size_t)r2 * C + cc) =
                    make_float2(acc[mt][nt][2], acc[mt][nt][3]);
        }

    if (SCORES) {
        // p[i]: i = mt*2 + j -> row warp_m*32 + mt*16 + j*8 + gid
        float p1[4] = {0.f, 0.f, 0.f, 0.f}, p2[4] = {0.f, 0.f, 0.f, 0.f};
#pragma unroll
        for (int mt = 0; mt < 2; ++mt)
#pragma unroll
            for (int nt = 0; nt < 4; ++nt) {
                int cc = warp_n * 32 + nt * 8 + tig * 2;
                float a1c0 = a1[cc], a1c1 = a1[cc + 1];
                float a2c0 = a2[cc], a2c1 = a2[cc + 1];
                p1[mt * 2 + 0] += acc[mt][nt][0] * a1c0 + acc[mt][nt][1] * a1c1;
                p1[mt * 2 + 1] += acc[mt][nt][2] * a1c0 + acc[mt][nt][3] * a1c1;
                p2[mt * 2 + 0] += acc[mt][nt][0] * a2c0 + acc[mt][nt][1] * a2c1;
                p2[mt * 2 + 1] += acc[mt][nt][2] * a2c0 + acc[mt][nt][3] * a2c1;
            }
#pragma unroll
        for (int o = 1; o <= 2; o <<= 1)
#pragma unroll
            for (int i = 0; i < 4; ++i) {
                p1[i] += __shfl_xor_sync(0xffffffffu, p1[i], o);
                p2[i] += __shfl_xor_sync(0xffffffffu, p2[i], o);
            }
        float* sred = reinterpret_cast<float*>(smem);   // [2][4][128] = 1024 floats
        if (tig == 0) {
#pragma unroll
            for (int i = 0; i < 4; ++i) {
                int r = warp_m * 32 + (i >> 1) * 16 + (i & 1) * 8 + gid;
                sred[warp_n * 128 + r]       = p1[i];
                sred[512 + warp_n * 128 + r] = p2[i];
            }
        }
        __syncthreads();
        if (tid < 128) {
            int grow = row0 + tid;
            if (grow < M) {
                g_s1[grow] = sred[tid] + sred[128 + tid] + sred[256 + tid] + sred[384 + tid];
                g_s2[grow] = sred[512 + tid] + sred[640 + tid] + sred[768 + tid] + sred[896 + tid];
            }
        }
    }
}

// ---------------- fused setup: detect dtype + zero cnt + split weights -------
__global__ void setup_kernel(const int* __restrict__ raw,
                             const float* __restrict__ W,
                             const float* __restrict__ Wout) {
    int stride = gridDim.x * blockDim.x;
    int i = blockIdx.x * blockDim.x + threadIdx.x;
    if (blockIdx.x == 0) {
        int nz = (raw[2 * threadIdx.x + 1] != 0) ? 1 : 0;
        int any = __syncthreads_or(nz);
        if (threadIdx.x == 0) g_is64 = any ? 0 : 1;
    }
    for (int t = i; t < NN; t += stride) g_cnt[t] = 0;
    for (int t = i; t < C * C; t += stride) {
        int n = t & (C - 1), k = t >> 7;
        float v = W[k * C + n];
        __nv_bfloat16 h = __float2bfloat16_rn(v);
        g_BtWHi[n * C + k] = h;
        g_BtWLo[n * C + k] = __float2bfloat16_rn(v - __bfloat162float(h));
    }
    for (int t = i; t < EK * C * C; t += stride) {
        int n = t & (C - 1), k = t >> 7;
        float v = Wout[k * C + n];
        __nv_bfloat16 h = __float2bfloat16_rn(v);
        g_BtOHi[n * (EK * C) + k] = h;
        g_BtOLo[n * (EK * C) + k] = __float2bfloat16_rn(v - __bfloat162float(h));
    }
}

// degree count only (reads dst half of raw)
__global__ void normalize_kernel(const int* __restrict__ raw) {
    int e = blockIdx.x * blockDim.x + threadIdx.x;
    if (e >= NE) return;
    int d = g_is64 ? raw[2 * NE + 2 * e] : raw[NE + e];
    atomicAdd(&g_cnt[d], 1);
}

__global__ __launch_bounds__(SCAN_T) void scan_kernel() {
    __shared__ int s[SCAN_T];
    const int PER = (NN + SCAN_T - 1) / SCAN_T;
    int tid = threadIdx.x;
    int base = tid * PER;
    int sum = 0;
    for (int j = 0; j < PER; j++) {
        int idx = base + j;
        if (idx < NN) sum += g_cnt[idx];
    }
    s[tid] = sum;
    __syncthreads();
    for (int off = 1; off < SCAN_T; off <<= 1) {
        int v = (tid >= off) ? s[tid - off] : 0;
        __syncthreads();
        s[tid] += v;
        __syncthreads();
    }
    int run = s[tid] - sum;
    for (int j = 0; j < PER; j++) {
        int idx = base + j;
        if (idx < NN) {
            g_off[idx] = run;
            g_pos[idx] = run;
            run += g_cnt[idx];
        }
    }
    if (tid == SCAN_T - 1) g_off[NN] = s[SCAN_T - 1];
}

// ex = exp(leakyrelu(s1+s2)*ef); pack {src, ex0..2} into CSR slot
__global__ void edge_prep_kernel(const int* __restrict__ raw,
                                 const float* __restrict__ ef) {
    int e = blockIdx.x * blockDim.x + threadIdx.x;
    if (e >= NE) return;
    int src, dst;
    if (g_is64) { src = raw[2 * e]; dst = raw[2 * NE + 2 * e]; }
    else        { src = raw[e];     dst = raw[NE + e]; }
    float v = g_s1[src] + g_s2[dst];
    v = (v >= 0.f) ? v : LRELU_ALPHA * v;
    float ex0 = __expf(v * ef[e * EK + 0]);
    float ex1 = __expf(v * ef[e * EK + 1]);
    float ex2 = __expf(v * ef[e * EK + 2]);
    int p = atomicAdd(&g_pos[dst], 1);
    g_edata[p] = make_float4(__int_as_float(src), ex0, ex1, ex2);
}

// gather: one warp per node; uniform-address edata broadcast loads
__global__ void aggregate_kernel() {
    int gw = (blockIdx.x * blockDim.x + threadIdx.x) >> 5;
    int lane = threadIdx.x & 31;
    if (gw >= NN) return;
    int beg = g_off[gw], end = g_off[gw + 1];

    float den0 = 0.f, den1 = 0.f, den2 = 0.f;
    float4 acc0 = make_float4(0.f, 0.f, 0.f, 0.f);
    float4 acc1 = acc0, acc2 = acc0;

#pragma unroll 4
    for (int t = beg; t < end; ++t) {
        float4 ed = __ldg(&g_edata[t]);            // same addr warp-wide: broadcast
        int   srcj = __float_as_int(ed.x);
        float4 w = __ldg(reinterpret_cast<const float4*>(g_Wh + (size_t)srcj * C) + lane);
        den0 += ed.y; den1 += ed.z; den2 += ed.w;
        acc0.x += w.x * ed.y; acc0.y += w.y * ed.y; acc0.z += w.z * ed.y; acc0.w += w.w * ed.y;
        acc1.x += w.x * ed.z; acc1.y += w.y * ed.z; acc1.z += w.z * ed.z; acc1.w += w.w * ed.z;
        acc2.x += w.x * ed.w; acc2.y += w.y * ed.w; acc2.z += w.z * ed.w; acc2.w += w.w * ed.w;
    }
    float inv0 = 1.f / (den0 + 1e-16f);
    float inv1 = 1.f / (den1 + 1e-16f);
    float inv2 = 1.f / (den2 + 1e-16f);
    acc0.x *= inv0; acc0.y *= inv0; acc0.z *= inv0; acc0.w *= inv0;
    acc1.x *= inv1; acc1.y *= inv1; acc1.z *= inv1; acc1.w *= inv1;
    acc2.x *= inv2; acc2.y *= inv2; acc2.z *= inv2; acc2.w *= inv2;

    float* base = g_agg + (size_t)gw * (EK * C);
    __stwt(reinterpret_cast<float4*>(base) + lane,         acc0);
    __stwt(reinterpret_cast<float4*>(base + C) + lane,     acc1);
    __stwt(reinterpret_cast<float4*>(base + 2 * C) + lane, acc2);
}

// ---------------- launch ------------------------------------------------------

extern "C" void kernel_launch(void* const* d_in, const int* in_sizes, int n_in,
                              void* d_out, int out_size) {
    const float* h    = (const float*)d_in[0];
    const int*   eraw = (const int*)d_in[1];
    const float* ef   = (const float*)d_in[2];
    const float* W    = (const float*)d_in[3];
    const float* a1   = (const float*)d_in[4];
    const float* a2   = (const float*)d_in[5];
    const float* Wout = (const float*)d_in[6];
    float*       out  = (float*)d_out;

    float *pWh, *pAgg;
    __nv_bfloat16 *pWHi, *pWLo, *pOHi, *pOLo;
    cudaGetSymbolAddress((void**)&pWh,  g_Wh);
    cudaGetSymbolAddress((void**)&pAgg, g_agg);
    cudaGetSymbolAddress((void**)&pWHi, g_BtWHi);
    cudaGetSymbolAddress((void**)&pWLo, g_BtWLo);
    cudaGetSymbolAddress((void**)&pOHi, g_BtOHi);
    cudaGetSymbolAddress((void**)&pOLo, g_BtOLo);

    const int MBLK = (NN + 127) / 128;
    const int SMEM = 2 * STAGE_BYTES;   // 81920

    cudaFuncSetAttribute((const void*)bf16gemm<128, true>,
                         cudaFuncAttributeMaxDynamicSharedMemorySize, SMEM);
    cudaFuncSetAttribute((const void*)bf16gemm<384, false>,
                         cudaFuncAttributeMaxDynamicSharedMemorySize, SMEM);

    setup_kernel<<<256, 256>>>(eraw, W, Wout);
    normalize_kernel<<<(NE + 255) / 256, 256>>>(eraw);
    scan_kernel<<<1, SCAN_T>>>();
    bf16gemm<128, true><<<MBLK, 512, SMEM>>>(h, pWHi, pWLo, pWh, NN, a1, a2);
    edge_prep_kernel<<<(NE + 255) / 256, 256>>>(eraw, ef);
    aggregate_kernel<<<(NN * 32 + 255) / 256, 256>>>();
    bf16gemm<384, false><<<MBLK, 512, SMEM>>>(pAgg, pOHi, pOLo, out, NN, nullptr, nullptr);
}

// round 15
// speedup vs baseline: 1.0499x; 1.0499x over previous
#include <cuda_runtime.h>
#include <cuda_bf16.h>
#include <cuda_fp16.h>
#include <cstdint>

#define NN 50000
#define NE 800000
#define C 128
#define EK 3
#define LRELU_ALPHA 0.2f
#define SCAN_T 1024
#define RSTRIDE 80          // smem row stride in bytes

// ---------------- scratch ----------------------------------------------------
__device__ float  g_Wh[(size_t)NN * C];
__device__ float  g_s1[NN], g_s2[NN];
__device__ float4 g_edata[NE];                 // {src_bits, ex0, ex1, ex2} CSR order
__device__ float  g_agg[(size_t)NN * EK * C];
__device__ int    g_cnt[NN], g_off[NN + 1], g_pos[NN];
__device__ int    g_is64;
__device__ __align__(16) __nv_bfloat16 g_BtWHi[C * C], g_BtWLo[C * C];   // GEMM1 weights
__device__ __align__(16) __half        g_BtOH[EK * C * C], g_BtOL[EK * C * C]; // GEMM2 fp16 hi/lo

// ---------------- tensor-core MMA macros --------------------------------------
#define MMA_BF16(c, a, b0, b1)                                                 \
    asm volatile(                                                              \
        "mma.sync.aligned.m16n8k16.row.col.f32.bf16.bf16.f32 "                 \
        "{%0,%1,%2,%3}, {%4,%5,%6,%7}, {%8,%9}, {%0,%1,%2,%3};"                \
        : "+f"(c[0]), "+f"(c[1]), "+f"(c[2]), "+f"(c[3])                       \
        : "r"(a[0]), "r"(a[1]), "r"(a[2]), "r"(a[3]), "r"(b0), "r"(b1))

#define MMA_F16(c, a, b0, b1)                                                  \
    asm volatile(                                                              \
        "mma.sync.aligned.m16n8k16.row.col.f32.f16.f16.f32 "                   \
        "{%0,%1,%2,%3}, {%4,%5,%6,%7}, {%8,%9}, {%0,%1,%2,%3};"                \
        : "+f"(c[0]), "+f"(c[1]), "+f"(c[2]), "+f"(c[3])                       \
        : "r"(a[0]), "r"(a[1]), "r"(a[2]), "r"(a[3]), "r"(b0), "r"(b1))

__device__ __forceinline__ uint pack_hi_bf(float x, float y, uint& lo_out) {
    __nv_bfloat16 hx = __float2bfloat16_rn(x);
    __nv_bfloat16 hy = __float2bfloat16_rn(y);
    float lx = x - __bfloat162float(hx);
    float ly = y - __bfloat162float(hy);
    __nv_bfloat16 lxb = __float2bfloat16_rn(lx);
    __nv_bfloat16 lyb = __float2bfloat16_rn(ly);
    lo_out = (uint)__bfloat16_as_ushort(lxb) | ((uint)__bfloat16_as_ushort(lyb) << 16);
    return (uint)__bfloat16_as_ushort(hx) | ((uint)__bfloat16_as_ushort(hy) << 16);
}
__device__ __forceinline__ uint pack2_f16(float x, float y) {
    __half2 v = __floats2half2_rn(x, y);
    return *reinterpret_cast<uint*>(&v);
}

// C[M,128] = A[M,KTOT] @ Bt[128,KTOT]^T
// MODE 0: bf16 3-term split (A split in-kernel, B pre-split)   -- rel err ~1e-6
// MODE 1: fp16 2-term (A single fp16, B pre-split fp16 hi/lo)  -- rel err ~3e-4
// 512 threads, 16 warps in a 4(M) x 4(N) grid, warp tile 32x32.
template <int KTOT, bool SCORES, int MODE>
__global__ __launch_bounds__(512) void tcgemm(
    const float* __restrict__ A,
    const void* __restrict__ BtHi, const void* __restrict__ BtLo,
    float* __restrict__ Cm, int M,
    const float* __restrict__ a1, const float* __restrict__ a2)
{
    extern __shared__ char smem[];
    const int NT = KTOT / 32;
    const int OFF_AL = 10240;                           // MODE 0 only
    const int OFF_BH = (MODE == 0) ? 20480 : 10240;
    const int OFF_BL = OFF_BH + 10240;
    const int SB     = (MODE == 0) ? 40960 : 30720;

    int tid = threadIdx.x, lane = tid & 31, wid = tid >> 5;
    int gid = lane >> 2, tig = lane & 3;
    int warp_m = wid & 3, warp_n = wid >> 2;
    int row0 = blockIdx.x * 128;

    float acc[2][4][4] = {};
    float4 av[2];
    uint4  bh4, bl4;

    auto ldg_tile = [&](int t) {
#pragma unroll
        for (int i = 0; i < 2; ++i) {
            int idx = tid + i * 512;
            int r = idx >> 3, c4 = idx & 7;
            int gr = row0 + r;
            av[i] = (gr < M)
                ? __ldcs(reinterpret_cast<const float4*>(A) + (size_t)gr * (KTOT / 4) + t * 8 + c4)
                : make_float4(0.f, 0.f, 0.f, 0.f);
        }
        {
            int n = tid >> 2, c8 = tid & 3;
            size_t base = ((size_t)n * KTOT + (size_t)t * 32) >> 3;
            bh4 = reinterpret_cast<const uint4*>(BtHi)[base + c8];
            bl4 = reinterpret_cast<const uint4*>(BtLo)[base + c8];
        }
    };
    auto sts_tile = [&](int s) {
        char* st = smem + s * SB;
#pragma unroll
        for (int i = 0; i < 2; ++i) {
            int idx = tid + i * 512;
            int r = idx >> 3, c4 = idx & 7;
            if (MODE == 0) {
                uint l01, l23;
                uint h01 = pack_hi_bf(av[i].x, av[i].y, l01);
                uint h23 = pack_hi_bf(av[i].z, av[i].w, l23);
                *reinterpret_cast<uint2*>(st + r * RSTRIDE + c4 * 8)          = make_uint2(h01, h23);
                *reinterpret_cast<uint2*>(st + OFF_AL + r * RSTRIDE + c4 * 8) = make_uint2(l01, l23);
            } else {
                uint h01 = pack2_f16(av[i].x, av[i].y);
                uint h23 = pack2_f16(av[i].z, av[i].w);
                *reinterpret_cast<uint2*>(st + r * RSTRIDE + c4 * 8) = make_uint2(h01, h23);
            }
        }
        {
            int n = tid >> 2, c8 = tid & 3;
            *reinterpret_cast<uint4*>(st + OFF_BH + n * RSTRIDE + c8 * 16) = bh4;
            *reinterpret_cast<uint4*>(st + OFF_BL + n * RSTRIDE + c8 * 16) = bl4;
        }
    };

    ldg_tile(0);
    sts_tile(0);
    __syncthreads();

    for (int t = 0; t < NT; ++t) {
        if (t + 1 < NT) ldg_tile(t + 1);
        const char* st = smem + (t & 1) * SB;
#pragma unroll
        for (int ks = 0; ks < 2; ++ks) {
            int kb = ks * 32;
            uint ah[2][4], al[2][4];
#pragma unroll
            for (int mt = 0; mt < 2; ++mt) {
                int r0 = warp_m * 32 + mt * 16 + gid;
                const char* p0 = st + r0 * RSTRIDE + kb + tig * 4;
                ah[mt][0] = *reinterpret_cast<const uint*>(p0);
                ah[mt][1] = *reinterpret_cast<const uint*>(p0 + 8 * RSTRIDE);
                ah[mt][2] = *reinterpret_cast<const uint*>(p0 + 16);
                ah[mt][3] = *reinterpret_cast<const uint*>(p0 + 8 * RSTRIDE + 16);
                if (MODE == 0) {
                    const char* p1 = p0 + OFF_AL;
                    al[mt][0] = *reinterpret_cast<const uint*>(p1);
                    al[mt][1] = *reinterpret_cast<const uint*>(p1 + 8 * RSTRIDE);
                    al[mt][2] = *reinterpret_cast<const uint*>(p1 + 16);
                    al[mt][3] = *reinterpret_cast<const uint*>(p1 + 8 * RSTRIDE + 16);
                }
            }
#pragma unroll
            for (int nt = 0; nt < 4; ++nt) {
                int n0 = warp_n * 32 + nt * 8 + gid;
                const char* q = st + OFF_BH + n0 * RSTRIDE + kb + tig * 4;
                uint b0h = *reinterpret_cast<const uint*>(q);
                uint b1h = *reinterpret_cast<const uint*>(q + 16);
                uint b0l = *reinterpret_cast<const uint*>(q + 10240);
                uint b1l = *reinterpret_cast<const uint*>(q + 10240 + 16);
#pragma unroll
                for (int mt = 0; mt < 2; ++mt) {
                    if (MODE == 0) {
                        MMA_BF16(acc[mt][nt], ah[mt], b0h, b1h);
                        MMA_BF16(acc[mt][nt], ah[mt], b0l, b1l);
                        MMA_BF16(acc[mt][nt], al[mt], b0h, b1h);
                    } else {
                        MMA_F16(acc[mt][nt], ah[mt], b0h, b1h);
                        MMA_F16(acc[mt][nt], ah[mt], b0l, b1l);
                    }
                }
            }
        }
        if (t + 1 < NT) sts_tile((t + 1) & 1);
        __syncthreads();
    }

    // C store
#pragma unroll
    for (int mt = 0; mt < 2; ++mt)
#pragma unroll
        for (int nt = 0; nt < 4; ++nt) {
            int r1 = row0 + warp_m * 32 + mt * 16 + gid;
            int r2 = r1 + 8;
            int cc = warp_n * 32 + nt * 8 + tig * 2;
            if (r1 < M)
                *reinterpret_cast<float2*>(Cm + (size_t)r1 * C + cc) =
                    make_float2(acc[mt][nt][0], acc[mt][nt][1]);
            if (r2 < M)
                *reinterpret_cast<float2*>(Cm + (size_t)r2 * C + cc) =
                    make_float2(acc[mt][nt][2], acc[mt][nt][3]);
        }

    if (SCORES) {
        float p1[4] = {0.f, 0.f, 0.f, 0.f}, p2[4] = {0.f, 0.f, 0.f, 0.f};
#pragma unroll
        for (int mt = 0; mt < 2; ++mt)
#pragma unroll
            for (int nt = 0; nt < 4; ++nt) {
                int cc = warp_n * 32 + nt * 8 + tig * 2;
                float a1c0 = a1[cc], a1c1 = a1[cc + 1];
                float a2c0 = a2[cc], a2c1 = a2[cc + 1];
                p1[mt * 2 + 0] += acc[mt][nt][0] * a1c0 + acc[mt][nt][1] * a1c1;
                p1[mt * 2 + 1] += acc[mt][nt][2] * a1c0 + acc[mt][nt][3] * a1c1;
                p2[mt * 2 + 0] += acc[mt][nt][0] * a2c0 + acc[mt][nt][1] * a2c1;
                p2[mt * 2 + 1] += acc[mt][nt][2] * a2c0 + acc[mt][nt][3] * a2c1;
            }
#pragma unroll
        for (int o = 1; o <= 2; o <<= 1)
#pragma unroll
            for (int i = 0; i < 4; ++i) {
                p1[i] += __shfl_xor_sync(0xffffffffu, p1[i], o);
                p2[i] += __shfl_xor_sync(0xffffffffu, p2[i], o);
            }
        float* sred = reinterpret_cast<float*>(smem);   // 1024 floats
        if (tig == 0) {
#pragma unroll
            for (int i = 0; i < 4; ++i) {
                int r = warp_m * 32 + (i >> 1) * 16 + (i & 1) * 8 + gid;
                sred[warp_n * 128 + r]       = p1[i];
                sred[512 + warp_n * 128 + r] = p2[i];
            }
        }
        __syncthreads();
        if (tid < 128) {
            int grow = row0 + tid;
            if (grow < M) {
                g_s1[grow] = sred[tid] + sred[128 + tid] + sred[256 + tid] + sred[384 + tid];
                g_s2[grow] = sred[512 + tid] + sred[640 + tid] + sred[768 + tid] + sred[896 + tid];
            }
        }
    }
}

// ---------------- fused setup: detect dtype + zero cnt + split weights -------
__global__ void setup_kernel(const int* __restrict__ raw,
                             const float* __restrict__ W,
                             const float* __restrict__ Wout) {
    int stride = gridDim.x * blockDim.x;
    int i = blockIdx.x * blockDim.x + threadIdx.x;
    if (blockIdx.x == 0) {
        int nz = (raw[2 * threadIdx.x + 1] != 0) ? 1 : 0;
        int any = __syncthreads_or(nz);
        if (threadIdx.x == 0) g_is64 = any ? 0 : 1;
    }
    for (int t = i; t < NN; t += stride) g_cnt[t] = 0;
    for (int t = i; t < C * C; t += stride) {
        int n = t & (C - 1), k = t >> 7;
        float v = W[k * C + n];
        __nv_bfloat16 h = __float2bfloat16_rn(v);
        g_BtWHi[n * C + k] = h;
        g_BtWLo[n * C + k] = __float2bfloat16_rn(v - __bfloat162float(h));
    }
    for (int t = i; t < EK * C * C; t += stride) {
        int n = t & (C - 1), k = t >> 7;
        float v = Wout[k * C + n];
        __half hh = __float2half_rn(v);
        g_BtOH[n * (EK * C) + k] = hh;
        g_BtOL[n * (EK * C) + k] = __float2half_rn(v - __half2float(hh));
    }
}

// degree count only (reads dst half of raw)
__global__ void normalize_kernel(const int* __restrict__ raw) {
    int e = blockIdx.x * blockDim.x + threadIdx.x;
    if (e >= NE) return;
    int d = g_is64 ? raw[2 * NE + 2 * e] : raw[NE + e];
    atomicAdd(&g_cnt[d], 1);
}

__global__ __launch_bounds__(SCAN_T) void scan_kernel() {
    __shared__ int s[SCAN_T];
    const int PER = (NN + SCAN_T - 1) / SCAN_T;
    int tid = threadIdx.x;
    int base = tid * PER;
    int sum = 0;
    for (int j = 0; j < PER; j++) {
        int idx = base + j;
        if (idx < NN) sum += g_cnt[idx];
    }
    s[tid] = sum;
    __syncthreads();
    for (int off = 1; off < SCAN_T; off <<= 1) {
        int v = (tid >= off) ? s[tid - off] : 0;
        __syncthreads();
        s[tid] += v;
        __syncthreads();
    }
    int run = s[tid] - sum;
    for (int j = 0; j < PER; j++) {
        int idx = base + j;
        if (idx < NN) {
            g_off[idx] = run;
            g_pos[idx] = run;
            run += g_cnt[idx];
        }
    }
    if (tid == SCAN_T - 1) g_off[NN] = s[SCAN_T - 1];
}

// ex = exp(leakyrelu(s1+s2)*ef); pack {src, ex0..2} into CSR slot
__global__ void edge_prep_kernel(const int* __restrict__ raw,
                                 const float* __restrict__ ef) {
    int e = blockIdx.x * blockDim.x + threadIdx.x;
    if (e >= NE) return;
    int src, dst;
    if (g_is64) { src = raw[2 * e]; dst = raw[2 * NE + 2 * e]; }
    else        { src = raw[e];     dst = raw[NE + e]; }
    float v = g_s1[src] + g_s2[dst];
    v = (v >= 0.f) ? v : LRELU_ALPHA * v;
    float ex0 = __expf(v * ef[e * EK + 0]);
    float ex1 = __expf(v * ef[e * EK + 1]);
    float ex2 = __expf(v * ef[e * EK + 2]);
    int p = atomicAdd(&g_pos[dst], 1);
    g_edata[p] = make_float4(__int_as_float(src), ex0, ex1, ex2);
}

// gather: one warp per node; uniform-address edata broadcast loads
__global__ void aggregate_kernel() {
    int gw = (blockIdx.x * blockDim.x + threadIdx.x) >> 5;
    int lane = threadIdx.x & 31;
    if (gw >= NN) return;
    int beg = g_off[gw], end = g_off[gw + 1];

    float den0 = 0.f, den1 = 0.f, den2 = 0.f;
    float4 acc0 = make_float4(0.f, 0.f, 0.f, 0.f);
    float4 acc1 = acc0, acc2 = acc0;

#pragma unroll 4
    for (int t = beg; t < end; ++t) {
        float4 ed = __ldg(&g_edata[t]);
        int   srcj = __float_as_int(ed.x);
        float4 w = __ldg(reinterpret_cast<const float4*>(g_Wh + (size_t)srcj * C) + lane);
        den0 += ed.y; den1 += ed.z; den2 += ed.w;
        acc0.x += w.x * ed.y; acc0.y += w.y * ed.y; acc0.z += w.z * ed.y; acc0.w += w.w * ed.y;
        acc1.x += w.x * ed.z; acc1.y += w.y * ed.z; acc1.z += w.z * ed.z; acc1.w += w.w * ed.z;
        acc2.x += w.x * ed.w; acc2.y += w.y * ed.w; acc2.z += w.z * ed.w; acc2.w += w.w * ed.w;
    }
    float inv0 = 1.f / (den0 + 1e-16f);
    float inv1 = 1.f / (den1 + 1e-16f);
    float inv2 = 1.f / (den2 + 1e-16f);
    acc0.x *= inv0; acc0.y *= inv0; acc0.z *= inv0; acc0.w *= inv0;
    acc1.x *= inv1; acc1.y *= inv1; acc1.z *= inv1; acc1.w *= inv1;
    acc2.x *= inv2; acc2.y *= inv2; acc2.z *= inv2; acc2.w *= inv2;

    float* base = g_agg + (size_t)gw * (EK * C);
    __stwt(reinterpret_cast<float4*>(base) + lane,         acc0);
    __stwt(reinterpret_cast<float4*>(base + C) + lane,     acc1);
    __stwt(reinterpret_cast<float4*>(base + 2 * C) + lane, acc2);
}

// ---------------- launch ------------------------------------------------------

extern "C" void kernel_launch(void* const* d_in, const int* in_sizes, int n_in,
                              void* d_out, int out_size) {
    const float* h    = (const float*)d_in[0];
    const int*   eraw = (const int*)d_in[1];
    const float* ef   = (const float*)d_in[2];
    const float* W    = (const float*)d_in[3];
    const float* a1   = (const float*)d_in[4];
    const float* a2   = (const float*)d_in[5];
    const float* Wout = (const float*)d_in[6];
    float*       out  = (float*)d_out;

    float *pWh, *pAgg;
    void *pWHi, *pWLo, *pOH, *pOL;
    cudaGetSymbolAddress((void**)&pWh,  g_Wh);
    cudaGetSymbolAddress((void**)&pAgg, g_agg);
    cudaGetSymbolAddress(&pWHi, g_BtWHi);
    cudaGetSymbolAddress(&pWLo, g_BtWLo);
    cudaGetSymbolAddress(&pOH,  g_BtOH);
    cudaGetSymbolAddress(&pOL,  g_BtOL);

    const int MBLK = (NN + 127) / 128;
    const int SMEM1 = 2 * 40960;   // MODE 0 stages
    const int SMEM2 = 2 * 30720;   // MODE 1 stages

    cudaFuncSetAttribute((const void*)tcgemm<128, true, 0>,
                         cudaFuncAttributeMaxDynamicSharedMemorySize, SMEM1);
    cudaFuncSetAttribute((const void*)tcgemm<384, false, 1>,
                         cudaFuncAttributeMaxDynamicSharedMemorySize, SMEM2);

    setup_kernel<<<256, 256>>>(eraw, W, Wout);
    normalize_kernel<<<(NE + 255) / 256, 256>>>(eraw);
    scan_kernel<<<1, SCAN_T>>>();
    tcgemm<128, true, 0><<<MBLK, 512, SMEM1>>>(h, pWHi, pWLo, pWh, NN, a1, a2);
    edge_prep_kernel<<<(NE + 255) / 256, 256>>>(eraw, ef);
    aggregate_kernel<<<(NN * 32 + 255) / 256, 256>>>();
    tcgemm<384, false, 1><<<MBLK, 512, SMEM2>>>(pAgg, pOH, pOL, out, NN, nullptr, nullptr);
}

// round 16
// speedup vs baseline: 1.0698x; 1.0190x over previous
#include <cuda_runtime.h>
#include <cuda_bf16.h>
#include <cuda_fp16.h>
#include <cstdint>

#define NN 50000
#define NE 800000
#define C 128
#define EK 3
#define LRELU_ALPHA 0.2f
#define SCAN_T 1024
#define RSTRIDE 80          // smem row stride in bytes

// ---------------- scratch ----------------------------------------------------
__device__ float  g_Wh[(size_t)NN * C];
__device__ float  g_s1[NN], g_s2[NN];
__device__ float4 g_edata[NE];                 // {src_bits, ex0, ex1, ex2} CSR order
__device__ __align__(16) __half g_aggH[(size_t)NN * EK * C];   // fp16 agg (38.4 MB)
__device__ int    g_cnt[NN], g_off[NN + 1], g_pos[NN];
__device__ int    g_is64;
__device__ __align__(16) __nv_bfloat16 g_BtWHi[C * C], g_BtWLo[C * C];          // GEMM1
__device__ __align__(16) __half        g_BtOH[EK * C * C], g_BtOL[EK * C * C];  // GEMM2 hi/lo

// ---------------- tensor-core MMA macros --------------------------------------
#define MMA_BF16(c, a, b0, b1)                                                 \
    asm volatile(                                                              \
        "mma.sync.aligned.m16n8k16.row.col.f32.bf16.bf16.f32 "                 \
        "{%0,%1,%2,%3}, {%4,%5,%6,%7}, {%8,%9}, {%0,%1,%2,%3};"                \
        : "+f"(c[0]), "+f"(c[1]), "+f"(c[2]), "+f"(c[3])                       \
        : "r"(a[0]), "r"(a[1]), "r"(a[2]), "r"(a[3]), "r"(b0), "r"(b1))

#define MMA_F16(c, a, b0, b1)                                                  \
    asm volatile(                                                              \
        "mma.sync.aligned.m16n8k16.row.col.f32.f16.f16.f32 "                   \
        "{%0,%1,%2,%3}, {%4,%5,%6,%7}, {%8,%9}, {%0,%1,%2,%3};"                \
        : "+f"(c[0]), "+f"(c[1]), "+f"(c[2]), "+f"(c[3])                       \
        : "r"(a[0]), "r"(a[1]), "r"(a[2]), "r"(a[3]), "r"(b0), "r"(b1))

__device__ __forceinline__ uint pack_hi_bf(float x, float y, uint& lo_out) {
    __nv_bfloat16 hx = __float2bfloat16_rn(x);
    __nv_bfloat16 hy = __float2bfloat16_rn(y);
    float lx = x - __bfloat162float(hx);
    float ly = y - __bfloat162float(hy);
    __nv_bfloat16 lxb = __float2bfloat16_rn(lx);
    __nv_bfloat16 lyb = __float2bfloat16_rn(ly);
    lo_out = (uint)__bfloat16_as_ushort(lxb) | ((uint)__bfloat16_as_ushort(lyb) << 16);
    return (uint)__bfloat16_as_ushort(hx) | ((uint)__bfloat16_as_ushort(hy) << 16);
}
__device__ __forceinline__ uint pack2_f16(float x, float y) {
    __half2 v = __floats2half2_rn(x, y);
    return *reinterpret_cast<uint*>(&v);
}

// C[M,128] = A[M,KTOT] @ Bt[128,KTOT]^T
// MODE 0: A fp32 (split to bf16 hi/lo in-kernel), B bf16 pre-split; 3 MMAs/k16.
// MODE 1: A fp16 in GMEM (direct copy to smem),  B fp16 pre-split; 2 MMAs/k16.
// 512 threads, 16 warps in a 4(M) x 4(N) grid, warp tile 32x32.
template <int KTOT, bool SCORES, int MODE>
__global__ __launch_bounds__(512) void tcgemm(
    const void* __restrict__ A,
    const void* __restrict__ BtHi, const void* __restrict__ BtLo,
    float* __restrict__ Cm, int M,
    const float* __restrict__ a1, const float* __restrict__ a2)
{
    extern __shared__ char smem[];
    const int NT = KTOT / 32;
    const int OFF_AL = 10240;                           // MODE 0 only
    const int OFF_BH = (MODE == 0) ? 20480 : 10240;
    const int OFF_BL = OFF_BH + 10240;
    const int SB     = (MODE == 0) ? 40960 : 30720;

    int tid = threadIdx.x, lane = tid & 31, wid = tid >> 5;
    int gid = lane >> 2, tig = lane & 3;
    int warp_m = wid & 3, warp_n = wid >> 2;
    int row0 = blockIdx.x * 128;

    float acc[2][4][4] = {};
    float4 av[2];            // MODE 0 staging
    uint4  ah16;             // MODE 1 staging (16B of fp16 A per thread)
    uint4  bh4, bl4;

    auto ldg_tile = [&](int t) {
        if (MODE == 0) {
#pragma unroll
            for (int i = 0; i < 2; ++i) {
                int idx = tid + i * 512;
                int r = idx >> 3, c4 = idx & 7;
                int gr = row0 + r;
                av[i] = (gr < M)
                    ? __ldcs(reinterpret_cast<const float4*>(A) + (size_t)gr * (KTOT / 4) + t * 8 + c4)
                    : make_float4(0.f, 0.f, 0.f, 0.f);
            }
        } else {
            int r = tid >> 2, c16 = tid & 3;       // 128 rows x 4 uint4 (64B/row)
            int gr = row0 + r;
            ah16 = (gr < M)
                ? __ldcs(reinterpret_cast<const uint4*>(A) + (size_t)gr * (KTOT / 8) + t * 4 + c16)
                : make_uint4(0u, 0u, 0u, 0u);
        }
        {
            int n = tid >> 2, c8 = tid & 3;
            size_t base = ((size_t)n * KTOT + (size_t)t * 32) >> 3;
            bh4 = reinterpret_cast<const uint4*>(BtHi)[base + c8];
            bl4 = reinterpret_cast<const uint4*>(BtLo)[base + c8];
        }
    };
    auto sts_tile = [&](int s) {
        char* st = smem + s * SB;
        if (MODE == 0) {
#pragma unroll
            for (int i = 0; i < 2; ++i) {
                int idx = tid + i * 512;
                int r = idx >> 3, c4 = idx & 7;
                uint l01, l23;
                uint h01 = pack_hi_bf(av[i].x, av[i].y, l01);
                uint h23 = pack_hi_bf(av[i].z, av[i].w, l23);
                *reinterpret_cast<uint2*>(st + r * RSTRIDE + c4 * 8)          = make_uint2(h01, h23);
                *reinterpret_cast<uint2*>(st + OFF_AL + r * RSTRIDE + c4 * 8) = make_uint2(l01, l23);
            }
        } else {
            int r = tid >> 2, c16 = tid & 3;
            *reinterpret_cast<uint4*>(st + r * RSTRIDE + c16 * 16) = ah16;
        }
        {
            int n = tid >> 2, c8 = tid & 3;
            *reinterpret_cast<uint4*>(st + OFF_BH + n * RSTRIDE + c8 * 16) = bh4;
            *reinterpret_cast<uint4*>(st + OFF_BL + n * RSTRIDE + c8 * 16) = bl4;
        }
    };

    ldg_tile(0);
    sts_tile(0);
    __syncthreads();

    for (int t = 0; t < NT; ++t) {
        if (t + 1 < NT) ldg_tile(t + 1);
        const char* st = smem + (t & 1) * SB;
#pragma unroll
        for (int ks = 0; ks < 2; ++ks) {
            int kb = ks * 32;
            uint ah[2][4], al[2][4];
#pragma unroll
            for (int mt = 0; mt < 2; ++mt) {
                int r0 = warp_m * 32 + mt * 16 + gid;
                const char* p0 = st + r0 * RSTRIDE + kb + tig * 4;
                ah[mt][0] = *reinterpret_cast<const uint*>(p0);
                ah[mt][1] = *reinterpret_cast<const uint*>(p0 + 8 * RSTRIDE);
                ah[mt][2] = *reinterpret_cast<const uint*>(p0 + 16);
                ah[mt][3] = *reinterpret_cast<const uint*>(p0 + 8 * RSTRIDE + 16);
                if (MODE == 0) {
                    const char* p1 = p0 + OFF_AL;
                    al[mt][0] = *reinterpret_cast<const uint*>(p1);
                    al[mt][1] = *reinterpret_cast<const uint*>(p1 + 8 * RSTRIDE);
                    al[mt][2] = *reinterpret_cast<const uint*>(p1 + 16);
                    al[mt][3] = *reinterpret_cast<const uint*>(p1 + 8 * RSTRIDE + 16);
                }
            }
#pragma unroll
            for (int nt = 0; nt < 4; ++nt) {
                int n0 = warp_n * 32 + nt * 8 + gid;
                const char* q = st + OFF_BH + n0 * RSTRIDE + kb + tig * 4;
                uint b0h = *reinterpret_cast<const uint*>(q);
                uint b1h = *reinterpret_cast<const uint*>(q + 16);
                uint b0l = *reinterpret_cast<const uint*>(q + 10240);
                uint b1l = *reinterpret_cast<const uint*>(q + 10240 + 16);
#pragma unroll
                for (int mt = 0; mt < 2; ++mt) {
                    if (MODE == 0) {
                        MMA_BF16(acc[mt][nt], ah[mt], b0h, b1h);
                        MMA_BF16(acc[mt][nt], ah[mt], b0l, b1l);
                        MMA_BF16(acc[mt][nt], al[mt], b0h, b1h);
                    } else {
                        MMA_F16(acc[mt][nt], ah[mt], b0h, b1h);
                        MMA_F16(acc[mt][nt], ah[mt], b0l, b1l);
                    }
                }
            }
        }
        if (t + 1 < NT) sts_tile((t + 1) & 1);
        __syncthreads();
    }

    // C store
#pragma unroll
    for (int mt = 0; mt < 2; ++mt)
#pragma unroll
        for (int nt = 0; nt < 4; ++nt) {
            int r1 = row0 + warp_m * 32 + mt * 16 + gid;
            int r2 = r1 + 8;
            int cc = warp_n * 32 + nt * 8 + tig * 2;
            if (r1 < M)
                *reinterpret_cast<float2*>(Cm + (size_t)r1 * C + cc) =
                    make_float2(acc[mt][nt][0], acc[mt][nt][1]);
            if (r2 < M)
                *reinterpret_cast<float2*>(Cm + (size_t)r2 * C + cc) =
                    make_float2(acc[mt][nt][2], acc[mt][nt][3]);
        }

    if (SCORES) {
        float p1[4] = {0.f, 0.f, 0.f, 0.f}, p2[4] = {0.f, 0.f, 0.f, 0.f};
#pragma unroll
        for (int mt = 0; mt < 2; ++mt)
#pragma unroll
            for (int nt = 0; nt < 4; ++nt) {
                int cc = warp_n * 32 + nt * 8 + tig * 2;
                float a1c0 = a1[cc], a1c1 = a1[cc + 1];
                float a2c0 = a2[cc], a2c1 = a2[cc + 1];
                p1[mt * 2 + 0] += acc[mt][nt][0] * a1c0 + acc[mt][nt][1] * a1c1;
                p1[mt * 2 + 1] += acc[mt][nt][2] * a1c0 + acc[mt][nt][3] * a1c1;
                p2[mt * 2 + 0] += acc[mt][nt][0] * a2c0 + acc[mt][nt][1] * a2c1;
                p2[mt * 2 + 1] += acc[mt][nt][2] * a2c0 + acc[mt][nt][3] * a2c1;
            }
#pragma unroll
        for (int o = 1; o <= 2; o <<= 1)
#pragma unroll
            for (int i = 0; i < 4; ++i) {
                p1[i] += __shfl_xor_sync(0xffffffffu, p1[i], o);
                p2[i] += __shfl_xor_sync(0xffffffffu, p2[i], o);
            }
        float* sred = reinterpret_cast<float*>(smem);
        if (tig == 0) {
#pragma unroll
            for (int i = 0; i < 4; ++i) {
                int r = warp_m * 32 + (i >> 1) * 16 + (i & 1) * 8 + gid;
                sred[warp_n * 128 + r]       = p1[i];
                sred[512 + warp_n * 128 + r] = p2[i];
            }
        }
        __syncthreads();
        if (tid < 128) {
            int grow = row0 + tid;
            if (grow < M) {
                g_s1[grow] = sred[tid] + sred[128 + tid] + sred[256 + tid] + sred[384 + tid];
                g_s2[grow] = sred[512 + tid] + sred[640 + tid] + sred[768 + tid] + sred[896 + tid];
            }
        }
    }
}

// ---------------- fused setup: detect dtype + zero cnt + split weights -------
__global__ void setup_kernel(const int* __restrict__ raw,
                             const float* __restrict__ W,
                             const float* __restrict__ Wout) {
    int stride = gridDim.x * blockDim.x;
    int i = blockIdx.x * blockDim.x + threadIdx.x;
    if (blockIdx.x == 0) {
        int nz = (raw[2 * threadIdx.x + 1] != 0) ? 1 : 0;
        int any = __syncthreads_or(nz);
        if (threadIdx.x == 0) g_is64 = any ? 0 : 1;
    }
    for (int t = i; t < NN; t += stride) g_cnt[t] = 0;
    for (int t = i; t < C * C; t += stride) {
        int n = t & (C - 1), k = t >> 7;
        float v = W[k * C + n];
        __nv_bfloat16 h = __float2bfloat16_rn(v);
        g_BtWHi[n * C + k] = h;
        g_BtWLo[n * C + k] = __float2bfloat16_rn(v - __bfloat162float(h));
    }
    for (int t = i; t < EK * C * C; t += stride) {
        int n = t & (C - 1), k = t >> 7;
        float v = Wout[k * C + n];
        __half hh = __float2half_rn(v);
        g_BtOH[n * (EK * C) + k] = hh;
        g_BtOL[n * (EK * C) + k] = __float2half_rn(v - __half2float(hh));
    }
}

// degree count only (reads dst half of raw)
__global__ void normalize_kernel(const int* __restrict__ raw) {
    int e = blockIdx.x * blockDim.x + threadIdx.x;
    if (e >= NE) return;
    int d = g_is64 ? raw[2 * NE + 2 * e] : raw[NE + e];
    atomicAdd(&g_cnt[d], 1);
}

__global__ __launch_bounds__(SCAN_T) void scan_kernel() {
    __shared__ int s[SCAN_T];
    const int PER = (NN + SCAN_T - 1) / SCAN_T;
    int tid = threadIdx.x;
    int base = tid * PER;
    int sum = 0;
    for (int j = 0; j < PER; j++) {
        int idx = base + j;
        if (idx < NN) sum += g_cnt[idx];
    }
    s[tid] = sum;
    __syncthreads();
    for (int off = 1; off < SCAN_T; off <<= 1) {
        int v = (tid >= off) ? s[tid - off] : 0;
        __syncthreads();
        s[tid] += v;
        __syncthreads();
    }
    int run = s[tid] - sum;
    for (int j = 0; j < PER; j++) {
        int idx = base + j;
        if (idx < NN) {
            g_off[idx] = run;
            g_pos[idx] = run;
            run += g_cnt[idx];
        }
    }
    if (tid == SCAN_T - 1) g_off[NN] = s[SCAN_T - 1];
}

// ex = exp(leakyrelu(s1+s2)*ef); pack {src, ex0..2} into CSR slot
__global__ void edge_prep_kernel(const int* __restrict__ raw,
                                 const float* __restrict__ ef) {
    int e = blockIdx.x * blockDim.x + threadIdx.x;
    if (e >= NE) return;
    int src, dst;
    if (g_is64) { src = raw[2 * e]; dst = raw[2 * NE + 2 * e]; }
    else        { src = raw[e];     dst = raw[NE + e]; }
    float v = g_s1[src] + g_s2[dst];
    v = (v >= 0.f) ? v : LRELU_ALPHA * v;
    float ex0 = __expf(v * ef[e * EK + 0]);
    float ex1 = __expf(v * ef[e * EK + 1]);
    float ex2 = __expf(v * ef[e * EK + 2]);
    int p = atomicAdd(&g_pos[dst], 1);
    g_edata[p] = make_float4(__int_as_float(src), ex0, ex1, ex2);
}

// gather: one warp per node; fp32 accumulate, fp16 store
__global__ void aggregate_kernel() {
    int gw = (blockIdx.x * blockDim.x + threadIdx.x) >> 5;
    int lane = threadIdx.x & 31;
    if (gw >= NN) return;
    int beg = g_off[gw], end = g_off[gw + 1];

    float den0 = 0.f, den1 = 0.f, den2 = 0.f;
    float4 acc0 = make_float4(0.f, 0.f, 0.f, 0.f);
    float4 acc1 = acc0, acc2 = acc0;

#pragma unroll 4
    for (int t = beg; t < end; ++t) {
        float4 ed = __ldg(&g_edata[t]);
        int   srcj = __float_as_int(ed.x);
        float4 w = __ldg(reinterpret_cast<const float4*>(g_Wh + (size_t)srcj * C) + lane);
        den0 += ed.y; den1 += ed.z; den2 += ed.w;
        acc0.x += w.x * ed.y; acc0.y += w.y * ed.y; acc0.z += w.z * ed.y; acc0.w += w.w * ed.y;
        acc1.x += w.x * ed.z; acc1.y += w.y * ed.z; acc1.z += w.z * ed.z; acc1.w += w.w * ed.z;
        acc2.x += w.x * ed.w; acc2.y += w.y * ed.w; acc2.z += w.z * ed.w; acc2.w += w.w * ed.w;
    }
    float inv0 = 1.f / (den0 + 1e-16f);
    float inv1 = 1.f / (den1 + 1e-16f);
    float inv2 = 1.f / (den2 + 1e-16f);

    __half* base = g_aggH + (size_t)gw * (EK * C);
    uint2 o0 = make_uint2(pack2_f16(acc0.x * inv0, acc0.y * inv0),
                          pack2_f16(acc0.z * inv0, acc0.w * inv0));
    uint2 o1 = make_uint2(pack2_f16(acc1.x * inv1, acc1.y * inv1),
                          pack2_f16(acc1.z * inv1, acc1.w * inv1));
    uint2 o2 = make_uint2(pack2_f16(acc2.x * inv2, acc2.y * inv2),
                          pack2_f16(acc2.z * inv2, acc2.w * inv2));
    __stwt(reinterpret_cast<uint2*>(base) + lane,           o0);
    __stwt(reinterpret_cast<uint2*>(base + C) + lane,       o1);
    __stwt(reinterpret_cast<uint2*>(base + 2 * C) + lane,   o2);
}

// ---------------- launch ------------------------------------------------------

extern "C" void kernel_launch(void* const* d_in, const int* in_sizes, int n_in,
                              void* d_out, int out_size) {
    const float* h    = (const float*)d_in[0];
    const int*   eraw = (const int*)d_in[1];
    const float* ef   = (const float*)d_in[2];
    const float* W    = (const float*)d_in[3];
    const float* a1   = (const float*)d_in[4];
    const float* a2   = (const float*)d_in[5];
    const float* Wout = (const float*)d_in[6];
    float*       out  = (float*)d_out;

    float *pWh;
    void *pAggH, *pWHi, *pWLo, *pOH, *pOL;
    cudaGetSymbolAddress((void**)&pWh,  g_Wh);
    cudaGetSymbolAddress(&pAggH, g_aggH);
    cudaGetSymbolAddress(&pWHi, g_BtWHi);
    cudaGetSymbolAddress(&pWLo, g_BtWLo);
    cudaGetSymbolAddress(&pOH,  g_BtOH);
    cudaGetSymbolAddress(&pOL,  g_BtOL);

    const int MBLK = (NN + 127) / 128;
    const int SMEM1 = 2 * 40960;   // MODE 0 stages
    const int SMEM2 = 2 * 30720;   // MODE 1 stages

    cudaFuncSetAttribute((const void*)tcgemm<128, true, 0>,
                         cudaFuncAttributeMaxDynamicSharedMemorySize, SMEM1);
    cudaFuncSetAttribute((const void*)tcgemm<384, false, 1>,
                         cudaFuncAttributeMaxDynamicSharedMemorySize, SMEM2);

    setup_kernel<<<256, 256>>>(eraw, W, Wout);
    normalize_kernel<<<(NE + 255) / 256, 256>>>(eraw);
    scan_kernel<<<1, SCAN_T>>>();
    tcgemm<128, true, 0><<<MBLK, 512, SMEM1>>>(h, pWHi, pWLo, pWh, NN, a1, a2);
    edge_prep_kernel<<<(NE + 255) / 256, 256>>>(eraw, ef);
    aggregate_kernel<<<(NN * 32 + 255) / 256, 256>>>();
    tcgemm<384, false, 1><<<MBLK, 512, SMEM2>>>(pAggH, pOH, pOL, out, NN, nullptr, nullptr);
}

// round 17
// speedup vs baseline: 1.1397x; 1.0653x over previous
#include <cuda_runtime.h>
#include <cuda_bf16.h>
#include <cuda_fp16.h>
#include <cstdint>

#define NN 50000
#define NE 800000
#define C 128
#define EK 3
#define LRELU_ALPHA 0.2f
#define SCAN_T 1024
#define RSTRIDE 80          // smem row stride in bytes

// ---------------- scratch ----------------------------------------------------
__device__ __align__(16) __half g_WhH[(size_t)NN * C];         // fp16 Wh (12.8 MB)
__device__ float  g_s1[NN], g_s2[NN];
__device__ float4 g_edata[NE];                 // {src_bits, ex0, ex1, ex2} CSR order
__device__ __align__(16) __half g_aggH[(size_t)NN * EK * C];   // fp16 agg (38.4 MB)
__device__ int    g_cnt[NN], g_off[NN + 1], g_pos[NN];
__device__ int    g_is64;
__device__ __align__(16) __nv_bfloat16 g_BtWHi[C * C], g_BtWLo[C * C];  // GEMM1 B
__device__ __align__(16) __half        g_BtOH[EK * C * C];              // GEMM2 B (single fp16)

// ---------------- tensor-core MMA macros --------------------------------------
#define MMA_BF16(c, a, b0, b1)                                                 \
    asm volatile(                                                              \
        "mma.sync.aligned.m16n8k16.row.col.f32.bf16.bf16.f32 "                 \
        "{%0,%1,%2,%3}, {%4,%5,%6,%7}, {%8,%9}, {%0,%1,%2,%3};"                \
        : "+f"(c[0]), "+f"(c[1]), "+f"(c[2]), "+f"(c[3])                       \
        : "r"(a[0]), "r"(a[1]), "r"(a[2]), "r"(a[3]), "r"(b0), "r"(b1))

#define MMA_F16(c, a, b0, b1)                                                  \
    asm volatile(                                                              \
        "mma.sync.aligned.m16n8k16.row.col.f32.f16.f16.f32 "                   \
        "{%0,%1,%2,%3}, {%4,%5,%6,%7}, {%8,%9}, {%0,%1,%2,%3};"                \
        : "+f"(c[0]), "+f"(c[1]), "+f"(c[2]), "+f"(c[3])                       \
        : "r"(a[0]), "r"(a[1]), "r"(a[2]), "r"(a[3]), "r"(b0), "r"(b1))

__device__ __forceinline__ uint pack_hi_bf(float x, float y, uint& lo_out) {
    __nv_bfloat16 hx = __float2bfloat16_rn(x);
    __nv_bfloat16 hy = __float2bfloat16_rn(y);
    float lx = x - __bfloat162float(hx);
    float ly = y - __bfloat162float(hy);
    __nv_bfloat16 lxb = __float2bfloat16_rn(lx);
    __nv_bfloat16 lyb = __float2bfloat16_rn(ly);
    lo_out = (uint)__bfloat16_as_ushort(lxb) | ((uint)__bfloat16_as_ushort(lyb) << 16);
    return (uint)__bfloat16_as_ushort(hx) | ((uint)__bfloat16_as_ushort(hy) << 16);
}
__device__ __forceinline__ uint pack2_f16(float x, float y) {
    __half2 v = __floats2half2_rn(x, y);
    return *reinterpret_cast<uint*>(&v);
}

// C[M,128] = A[M,KTOT] @ Bt[128,KTOT]^T
// MODE 0: A fp32 (split to bf16 hi/lo in-kernel), B bf16 pre-split; 3 MMAs/k16.
//         C stored as fp16 (g_WhH). Scores epilogue from fp32 accumulators.
// MODE 1: A fp16 in GMEM (direct copy), B single fp16; 1 MMA/k16. C stored fp32.
// 512 threads, 16 warps in a 4(M) x 4(N) grid, warp tile 32x32.
template <int KTOT, bool SCORES, int MODE>
__global__ __launch_bounds__(512) void tcgemm(
    const void* __restrict__ A,
    const void* __restrict__ BtHi, const void* __restrict__ BtLo,
    void* __restrict__ Cm, int M,
    const float* __restrict__ a1, const float* __restrict__ a2)
{
    extern __shared__ char smem[];
    const int NT = KTOT / 32;
    const int OFF_AL = 10240;                           // MODE 0 only
    const int OFF_BH = (MODE == 0) ? 20480 : 10240;
    const int OFF_BL = OFF_BH + 10240;                  // MODE 0 only
    const int SB     = (MODE == 0) ? 40960 : 20480;

    int tid = threadIdx.x, lane = tid & 31, wid = tid >> 5;
    int gid = lane >> 2, tig = lane & 3;
    int warp_m = wid & 3, warp_n = wid >> 2;
    int row0 = blockIdx.x * 128;

    float acc[2][4][4] = {};
    float4 av[2];            // MODE 0 staging
    uint4  ah16;             // MODE 1 staging
    uint4  bh4, bl4;

    auto ldg_tile = [&](int t) {
        if (MODE == 0) {
#pragma unroll
            for (int i = 0; i < 2; ++i) {
                int idx = tid + i * 512;
                int r = idx >> 3, c4 = idx & 7;
                int gr = row0 + r;
                av[i] = (gr < M)
                    ? __ldcs(reinterpret_cast<const float4*>(A) + (size_t)gr * (KTOT / 4) + t * 8 + c4)
                    : make_float4(0.f, 0.f, 0.f, 0.f);
            }
        } else {
            int r = tid >> 2, c16 = tid & 3;
            int gr = row0 + r;
            ah16 = (gr < M)
                ? __ldcs(reinterpret_cast<const uint4*>(A) + (size_t)gr * (KTOT / 8) + t * 4 + c16)
                : make_uint4(0u, 0u, 0u, 0u);
        }
        {
            int n = tid >> 2, c8 = tid & 3;
            size_t base = ((size_t)n * KTOT + (size_t)t * 32) >> 3;
            bh4 = reinterpret_cast<const uint4*>(BtHi)[base + c8];
            if (MODE == 0) bl4 = reinterpret_cast<const uint4*>(BtLo)[base + c8];
        }
    };
    auto sts_tile = [&](int s) {
        char* st = smem + s * SB;
        if (MODE == 0) {
#pragma unroll
            for (int i = 0; i < 2; ++i) {
                int idx = tid + i * 512;
                int r = idx >> 3, c4 = idx & 7;
                uint l01, l23;
                uint h01 = pack_hi_bf(av[i].x, av[i].y, l01);
                uint h23 = pack_hi_bf(av[i].z, av[i].w, l23);
                *reinterpret_cast<uint2*>(st + r * RSTRIDE + c4 * 8)          = make_uint2(h01, h23);
                *reinterpret_cast<uint2*>(st + OFF_AL + r * RSTRIDE + c4 * 8) = make_uint2(l01, l23);
            }
        } else {
            int r = tid >> 2, c16 = tid & 3;
            *reinterpret_cast<uint4*>(st + r * RSTRIDE + c16 * 16) = ah16;
        }
        {
            int n = tid >> 2, c8 = tid & 3;
            *reinterpret_cast<uint4*>(st + OFF_BH + n * RSTRIDE + c8 * 16) = bh4;
            if (MODE == 0)
                *reinterpret_cast<uint4*>(st + OFF_BL + n * RSTRIDE + c8 * 16) = bl4;
        }
    };

    ldg_tile(0);
    sts_tile(0);
    __syncthreads();

    for (int t = 0; t < NT; ++t) {
        if (t + 1 < NT) ldg_tile(t + 1);
        const char* st = smem + (t & 1) * SB;
#pragma unroll
        for (int ks = 0; ks < 2; ++ks) {
            int kb = ks * 32;
            uint ah[2][4], al[2][4];
#pragma unroll
            for (int mt = 0; mt < 2; ++mt) {
                int r0 = warp_m * 32 + mt * 16 + gid;
                const char* p0 = st + r0 * RSTRIDE + kb + tig * 4;
                ah[mt][0] = *reinterpret_cast<const uint*>(p0);
                ah[mt][1] = *reinterpret_cast<const uint*>(p0 + 8 * RSTRIDE);
                ah[mt][2] = *reinterpret_cast<const uint*>(p0 + 16);
                ah[mt][3] = *reinterpret_cast<const uint*>(p0 + 8 * RSTRIDE + 16);
                if (MODE == 0) {
                    const char* p1 = p0 + OFF_AL;
                    al[mt][0] = *reinterpret_cast<const uint*>(p1);
                    al[mt][1] = *reinterpret_cast<const uint*>(p1 + 8 * RSTRIDE);
                    al[mt][2] = *reinterpret_cast<const uint*>(p1 + 16);
                    al[mt][3] = *reinterpret_cast<const uint*>(p1 + 8 * RSTRIDE + 16);
                }
            }
#pragma unroll
            for (int nt = 0; nt < 4; ++nt) {
                int n0 = warp_n * 32 + nt * 8 + gid;
                const char* q = st + OFF_BH + n0 * RSTRIDE + kb + tig * 4;
                uint b0h = *reinterpret_cast<const uint*>(q);
                uint b1h = *reinterpret_cast<const uint*>(q + 16);
#pragma unroll
                for (int mt = 0; mt < 2; ++mt) {
                    if (MODE == 0) {
                        uint b0l = *reinterpret_cast<const uint*>(q + 10240);
                        uint b1l = *reinterpret_cast<const uint*>(q + 10240 + 16);
                        MMA_BF16(acc[mt][nt], ah[mt], b0h, b1h);
                        MMA_BF16(acc[mt][nt], ah[mt], b0l, b1l);
                        MMA_BF16(acc[mt][nt], al[mt], b0h, b1h);
                    } else {
                        MMA_F16(acc[mt][nt], ah[mt], b0h, b1h);
                    }
                }
            }
        }
        if (t + 1 < NT) sts_tile((t + 1) & 1);
        __syncthreads();
    }

    // C store: MODE 0 -> fp16 (g_WhH), MODE 1 -> fp32 (out)
#pragma unroll
    for (int mt = 0; mt < 2; ++mt)
#pragma unroll
        for (int nt = 0; nt < 4; ++nt) {
            int r1 = row0 + warp_m * 32 + mt * 16 + gid;
            int r2 = r1 + 8;
            int cc = warp_n * 32 + nt * 8 + tig * 2;
            if (MODE == 0) {
                __half* Ch = reinterpret_cast<__half*>(Cm);
                if (r1 < M)
                    *reinterpret_cast<uint*>(Ch + (size_t)r1 * C + cc) =
                        pack2_f16(acc[mt][nt][0], acc[mt][nt][1]);
                if (r2 < M)
                    *reinterpret_cast<uint*>(Ch + (size_t)r2 * C + cc) =
                        pack2_f16(acc[mt][nt][2], acc[mt][nt][3]);
            } else {
                float* Cf = reinterpret_cast<float*>(Cm);
                if (r1 < M)
                    *reinterpret_cast<float2*>(Cf + (size_t)r1 * C + cc) =
                        make_float2(acc[mt][nt][0], acc[mt][nt][1]);
                if (r2 < M)
                    *reinterpret_cast<float2*>(Cf + (size_t)r2 * C + cc) =
                        make_float2(acc[mt][nt][2], acc[mt][nt][3]);
            }
        }

    if (SCORES) {
        float p1[4] = {0.f, 0.f, 0.f, 0.f}, p2[4] = {0.f, 0.f, 0.f, 0.f};
#pragma unroll
        for (int mt = 0; mt < 2; ++mt)
#pragma unroll
            for (int nt = 0; nt < 4; ++nt) {
                int cc = warp_n * 32 + nt * 8 + tig * 2;
                float a1c0 = a1[cc], a1c1 = a1[cc + 1];
                float a2c0 = a2[cc], a2c1 = a2[cc + 1];
                p1[mt * 2 + 0] += acc[mt][nt][0] * a1c0 + acc[mt][nt][1] * a1c1;
                p1[mt * 2 + 1] += acc[mt][nt][2] * a1c0 + acc[mt][nt][3] * a1c1;
                p2[mt * 2 + 0] += acc[mt][nt][0] * a2c0 + acc[mt][nt][1] * a2c1;
                p2[mt * 2 + 1] += acc[mt][nt][2] * a2c0 + acc[mt][nt][3] * a2c1;
            }
#pragma unroll
        for (int o = 1; o <= 2; o <<= 1)
#pragma unroll
            for (int i = 0; i < 4; ++i) {
                p1[i] += __shfl_xor_sync(0xffffffffu, p1[i], o);
                p2[i] += __shfl_xor_sync(0xffffffffu, p2[i], o);
            }
        float* sred = reinterpret_cast<float*>(smem);
        if (tig == 0) {
#pragma unroll
            for (int i = 0; i < 4; ++i) {
                int r = warp_m * 32 + (i >> 1) * 16 + (i & 1) * 8 + gid;
                sred[warp_n * 128 + r]       = p1[i];
                sred[512 + warp_n * 128 + r] = p2[i];
            }
        }
        __syncthreads();
        if (tid < 128) {
            int grow = row0 + tid;
            if (grow < M) {
                g_s1[grow] = sred[tid] + sred[128 + tid] + sred[256 + tid] + sred[384 + tid];
                g_s2[grow] = sred[512 + tid] + sred[640 + tid] + sred[768 + tid] + sred[896 + tid];
            }
        }
    }
}

// ---------------- fused setup: detect dtype + zero cnt + split weights -------
__global__ void setup_kernel(const int* __restrict__ raw,
                             const float* __restrict__ W,
                             const float* __restrict__ Wout) {
    int stride = gridDim.x * blockDim.x;
    int i = blockIdx.x * blockDim.x + threadIdx.x;
    if (blockIdx.x == 0) {
        int nz = (raw[2 * threadIdx.x + 1] != 0) ? 1 : 0;
        int any = __syncthreads_or(nz);
        if (threadIdx.x == 0) g_is64 = any ? 0 : 1;
    }
    for (int t = i; t < NN; t += stride) g_cnt[t] = 0;
    for (int t = i; t < C * C; t += stride) {
        int n = t & (C - 1), k = t >> 7;
        float v = W[k * C + n];
        __nv_bfloat16 h = __float2bfloat16_rn(v);
        g_BtWHi[n * C + k] = h;
        g_BtWLo[n * C + k] = __float2bfloat16_rn(v - __bfloat162float(h));
    }
    for (int t = i; t < EK * C * C; t += stride) {
        int n = t & (C - 1), k = t >> 7;
        g_BtOH[n * (EK * C) + k] = __float2half_rn(Wout[k * C + n]);
    }
}

// degree count only (reads dst half of raw)
__global__ void normalize_kernel(const int* __restrict__ raw) {
    int e = blockIdx.x * blockDim.x + threadIdx.x;
    if (e >= NE) return;
    int d = g_is64 ? raw[2 * NE + 2 * e] : raw[NE + e];
    atomicAdd(&g_cnt[d], 1);
}

__global__ __launch_bounds__(SCAN_T) void scan_kernel() {
    __shared__ int s[SCAN_T];
    const int PER = (NN + SCAN_T - 1) / SCAN_T;
    int tid = threadIdx.x;
    int base = tid * PER;
    int sum = 0;
    for (int j = 0; j < PER; j++) {
        int idx = base + j;
        if (idx < NN) sum += g_cnt[idx];
    }
    s[tid] = sum;
    __syncthreads();
    for (int off = 1; off < SCAN_T; off <<= 1) {
        int v = (tid >= off) ? s[tid - off] : 0;
        __syncthreads();
        s[tid] += v;
        __syncthreads();
    }
    int run = s[tid] - sum;
    for (int j = 0; j < PER; j++) {
        int idx = base + j;
        if (idx < NN) {
            g_off[idx] = run;
            g_pos[idx] = run;
            run += g_cnt[idx];
        }
    }
    if (tid == SCAN_T - 1) g_off[NN] = s[SCAN_T - 1];
}

// ex = exp(leakyrelu(s1+s2)*ef); pack {src, ex0..2} into CSR slot
__global__ void edge_prep_kernel(const int* __restrict__ raw,
                                 const float* __restrict__ ef) {
    int e = blockIdx.x * blockDim.x + threadIdx.x;
    if (e >= NE) return;
    int src, dst;
    if (g_is64) { src = raw[2 * e]; dst = raw[2 * NE + 2 * e]; }
    else        { src = raw[e];     dst = raw[NE + e]; }
    float v = g_s1[src] + g_s2[dst];
    v = (v >= 0.f) ? v : LRELU_ALPHA * v;
    float ex0 = __expf(v * ef[e * EK + 0]);
    float ex1 = __expf(v * ef[e * EK + 1]);
    float ex2 = __expf(v * ef[e * EK + 2]);
    int p = atomicAdd(&g_pos[dst], 1);
    g_edata[p] = make_float4(__int_as_float(src), ex0, ex1, ex2);
}

// gather: one warp per node; fp16 Wh rows (8B/lane), fp32 accumulate, fp16 store
__global__ void aggregate_kernel() {
    int gw = (blockIdx.x * blockDim.x + threadIdx.x) >> 5;
    int lane = threadIdx.x & 31;
    if (gw >= NN) return;
    int beg = g_off[gw], end = g_off[gw + 1];

    float den0 = 0.f, den1 = 0.f, den2 = 0.f;
    float4 acc0 = make_float4(0.f, 0.f, 0.f, 0.f);
    float4 acc1 = acc0, acc2 = acc0;

#pragma unroll 4
    for (int t = beg; t < end; ++t) {
        float4 ed = __ldg(&g_edata[t]);
        int   srcj = __float_as_int(ed.x);
        uint2 wp = __ldg(reinterpret_cast<const uint2*>(g_WhH + (size_t)srcj * C) + lane);
        float2 f0 = __half22float2(*reinterpret_cast<__half2*>(&wp.x));
        float2 f1 = __half22float2(*reinterpret_cast<__half2*>(&wp.y));
        den0 += ed.y; den1 += ed.z; den2 += ed.w;
        acc0.x += f0.x * ed.y; acc0.y += f0.y * ed.y; acc0.z += f1.x * ed.y; acc0.w += f1.y * ed.y;
        acc1.x += f0.x * ed.z; acc1.y += f0.y * ed.z; acc1.z += f1.x * ed.z; acc1.w += f1.y * ed.z;
        acc2.x += f0.x * ed.w; acc2.y += f0.y * ed.w; acc2.z += f1.x * ed.w; acc2.w += f1.y * ed.w;
    }
    float inv0 = 1.f / (den0 + 1e-16f);
    float inv1 = 1.f / (den1 + 1e-16f);
    float inv2 = 1.f / (den2 + 1e-16f);

    __half* base = g_aggH + (size_t)gw * (EK * C);
    uint2 o0 = make_uint2(pack2_f16(acc0.x * inv0, acc0.y * inv0),
                          pack2_f16(acc0.z * inv0, acc0.w * inv0));
    uint2 o1 = make_uint2(pack2_f16(acc1.x * inv1, acc1.y * inv1),
                          pack2_f16(acc1.z * inv1, acc1.w * inv1));
    uint2 o2 = make_uint2(pack2_f16(acc2.x * inv2, acc2.y * inv2),
                          pack2_f16(acc2.z * inv2, acc2.w * inv2));
    __stwt(reinterpret_cast<uint2*>(base) + lane,           o0);
    __stwt(reinterpret_cast<uint2*>(base + C) + lane,       o1);
    __stwt(reinterpret_cast<uint2*>(base + 2 * C) + lane,   o2);
}

// ---------------- launch ------------------------------------------------------

extern "C" void kernel_launch(void* const* d_in, const int* in_sizes, int n_in,
                              void* d_out, int out_size) {
    const float* h    = (const float*)d_in[0];
    const int*   eraw = (const int*)d_in[1];
    const float* ef   = (const float*)d_in[2];
    const float* W    = (const float*)d_in[3];
    const float* a1   = (const float*)d_in[4];
    const float* a2   = (const float*)d_in[5];
    const float* Wout = (const float*)d_in[6];

    void *pWhH, *pAggH, *pWHi, *pWLo, *pOH;
    cudaGetSymbolAddress(&pWhH, g_WhH);
    cudaGetSymbolAddress(&pAggH, g_aggH);
    cudaGetSymbolAddress(&pWHi, g_BtWHi);
    cudaGetSymbolAddress(&pWLo, g_BtWLo);
    cudaGetSymbolAddress(&pOH,  g_BtOH);

    const int MBLK = (NN + 127) / 128;
    const int SMEM1 = 2 * 40960;   // MODE 0 stages
    const int SMEM2 = 2 * 20480;   // MODE 1 stages

    cudaFuncSetAttribute((const void*)tcgemm<128, true, 0>,
                         cudaFuncAttributeMaxDynamicSharedMemorySize, SMEM1);
    cudaFuncSetAttribute((const void*)tcgemm<384, false, 1>,
                         cudaFuncAttributeMaxDynamicSharedMemorySize, SMEM2);

    setup_kernel<<<256, 256>>>(eraw, W, Wout);
    normalize_kernel<<<(NE + 255) / 256, 256>>>(eraw);
    scan_kernel<<<1, SCAN_T>>>();
    tcgemm<128, true, 0><<<MBLK, 512, SMEM1>>>(h, pWHi, pWLo, pWhH, NN, a1, a2);
    edge_prep_kernel<<<(NE + 255) / 256, 256>>>(eraw, ef);
    aggregate_kernel<<<(NN * 32 + 255) / 256, 256>>>();
    tcgemm<384, false, 1><<<MBLK, 512, SMEM2>>>(pAggH, pOH, nullptr, d_out, NN, nullptr, nullptr);
}